// round 12
// baseline (speedup 1.0000x reference)
#include <cuda_runtime.h>
#include <math.h>
#include <stdint.h>

#define NRBF 32
#define RCAP 131072
__device__ float4 g_R4[RCAP];
__device__ unsigned g_init_ctr = 0;
__device__ unsigned g_done_ctr = 0;

// step = 5/31, width = 5/32
#define STEP      (0.16129032258064516f)
#define INV_W     (6.4f)
#define S_RATIO   (1.03225806451612903f)   // step/width
#define HALF_S2   (0.53277835587929240f)   // 0.5*(step/width)^2
#define G_CONST   (0.34453600290f)         // exp(-(step/width)^2)
#define R_CUTF    (5.0f)
#define U0_MAX    (13.0f)

#define C1  (0.48860251190291992f)
#define C2A (1.09254843059207907f)
#define C2B (0.31539156525252005f)
#define C2C (0.54627421529603953f)

#define PAIRS_PER_BLOCK 128
#define INIT_BLOCKS 256           // << wave-1 residency (148 SMs x 6): no deadlock

// FMA/ALU-only expf (no MUFU). Valid for x in [-85, +14].
__device__ __forceinline__ float fast_exp(float x) {
    float t  = x * 1.44269504f;
    float fi = rintf(t);
    int   ei = (int)fi;
    float g  = fmaf(fi, -0.693147182f, x);
    float p  = 1.9875691500e-4f;
    p = fmaf(p, g, 1.3981999507e-3f);
    p = fmaf(p, g, 8.3334519073e-3f);
    p = fmaf(p, g, 4.1665795894e-2f);
    p = fmaf(p, g, 1.6666665459e-1f);
    p = fmaf(p, g, 5.0000001201e-1f);
    float e = fmaf(g * g, p, g) + 1.0f;
    return __int_as_float(__float_as_int(e) + (ei << 23));
}

// ---------------------------------------------------------------------------
// Fused kernel: init (blocks < INIT_BLOCKS pack R + zero chi) + device barrier
// + geo. FULL blocks only (n_pairs % 128 == 0). Store path: rotated STS +
// cp.async.bulk (proven in rounds 7-10).
// ---------------------------------------------------------------------------
__global__ void __launch_bounds__(256, 6)
geo_fused(const float* __restrict__ Rraw,
          const float* __restrict__ pair_mask,
          const float* __restrict__ point_mask,
          const int*   __restrict__ idx_i,
          const int*   __restrict__ idx_j,
          float* __restrict__ rbf_out,
          float* __restrict__ chi_out,
          int n_points)
{
    __shared__ __align__(16) float tile[PAIRS_PER_BLOCK * NRBF];

    const unsigned tid  = threadIdx.x;
    const unsigned lane = tid & 31u;
    const unsigned s    = tid >> 1;
    const unsigned h    = tid & 1u;
    const unsigned p    = blockIdx.x * (unsigned)PAIRS_PER_BLOCK + s;

    // ---- fused init: pack R + zero chi (blocks 0..INIT_BLOCKS-1) ----
    if (blockIdx.x < INIT_BLOCKS) {
        float4* chi4 = (float4*)chi_out;
        const float4 z = make_float4(0.f, 0.f, 0.f, 0.f);
        for (unsigned pt = blockIdx.x * 256u + tid; pt < (unsigned)n_points;
             pt += INIT_BLOCKS * 256u) {
            g_R4[pt] = make_float4(Rraw[3u*pt], Rraw[3u*pt + 1],
                                   Rraw[3u*pt + 2], 0.f);
            chi4[2u*pt]     = z;
            chi4[2u*pt + 1] = z;
        }
        __syncthreads();
        if (tid == 0) {
            __threadfence();                       // release all init stores
            atomicAdd(&g_init_ctr, 1u);
        }
    }

    // loads independent of init: issue before the barrier
    const int   i   = __ldg(idx_i + p);
    const int   j   = __ldg(idx_j + p);
    const float pm  = __ldg(pair_mask + p);
    const float pmi = __ldg(point_mask + i);

    // ---- acquire-spin until all init blocks are done ----
    if (tid == 0) {
        unsigned v;
        do {
            asm volatile("ld.acquire.gpu.global.u32 %0, [%1];"
                         : "=r"(v) : "l"(&g_init_ctr) : "memory");
            if (v < INIT_BLOCKS) __nanosleep(128);
        } while (v < INIT_BLOCKS);
    }
    __syncthreads();

    // COHERENT loads of g_R4 (written this launch: __ldg contract forbids nc)
    const float4 a = g_R4[j];
    const float4 b = g_R4[i];
    const float rx = (a.x - b.x) * pm;
    const float ry = (a.y - b.y) * pm;
    const float rz = (a.z - b.z) * pm;

    const float sq  = fmaf(rx, rx, fmaf(ry, ry, rz * rz));
    const float inv = (sq > 0.f) ? rsqrtf(sq) : 0.f;
    const float d   = sq * inv * pm;

    // ---- rbf half-row: anchor at k = 16h+8, two-sided ladder ----
    const float cm   = (float)(16u * h + 8u) * STEP;
    const float u0   = (d - cm) * INV_W;
    const float u0r  = fminf(fmaxf(u0, -U0_MAX), U0_MAX);
    const float kill = (fabsf(u0) < U0_MAX) ? pm : 0.f;
    const float A  = fast_exp(-0.5f * u0r * u0r) * kill;
    const float qu = fast_exp(fmaf(u0r, S_RATIO, -HALF_S2));
    float rq = __uint_as_float(0x7EF311C3u - __float_as_uint(qu));
    rq = rq * (2.0f - qu * rq);
    rq = rq * (2.0f - qu * rq);
    rq = rq * (2.0f - qu * rq);
    const float qd = G_CONST * rq;

    float x[16];
    x[8] = A;
    {
        float r = A, q = qd;
        #pragma unroll
        for (int m = 7; m >= 0; --m) { r *= q; q *= G_CONST; x[m] = r; }
    }
    {
        float r = A, q = qu;
        #pragma unroll
        for (int m = 9; m < 16; ++m) { r *= q; q *= G_CONST; x[m] = r; }
    }

    // ---- rotated STS: slot t stores quad (t+s)&3 (conflict-free phases) ----
    {
        const float4 Q0 = make_float4(x[0],  x[1],  x[2],  x[3]);
        const float4 Q1 = make_float4(x[4],  x[5],  x[6],  x[7]);
        const float4 Q2 = make_float4(x[8],  x[9],  x[10], x[11]);
        const float4 Q3 = make_float4(x[12], x[13], x[14], x[15]);
        char* rowp = (char*)tile + (s * 128u + h * 64u);
        #pragma unroll
        for (unsigned t = 0; t < 4; ++t) {
            unsigned q = (t + s) & 3u;
            float4 a0 = (q & 1u) ? Q1 : Q0;
            float4 a1 = (q & 1u) ? Q3 : Q2;
            float4 r  = (q & 2u) ? a1 : a0;
            *(float4*)(rowp + q * 16u) = r;
        }
    }

    // ---- kick off the bulk copy NOW; chi work below overlaps the DMA ----
    __syncthreads();
    if (tid == 0) {
        asm volatile("fence.proxy.async.shared::cta;" ::: "memory");
        size_t p0 = (size_t)blockIdx.x * PAIRS_PER_BLOCK;
        unsigned bytes = PAIRS_PER_BLOCK * NRBF * 4;
        uint32_t saddr;
        asm("{ .reg .u64 t; cvta.to.shared.u64 t, %1; cvt.u32.u64 %0, t; }"
            : "=r"(saddr) : "l"(tile));
        unsigned long long gaddr = (unsigned long long)(rbf_out + p0 * NRBF);
        asm volatile("cp.async.bulk.global.shared::cta.bulk_group [%0], [%1], %2;"
                     :: "l"(gaddr), "r"(saddr), "r"(bytes) : "memory");
        asm volatile("cp.async.bulk.commit_group;" ::: "memory");
    }

    // ---- phi (cutoff): cos(pi*x) = -sin(pi*(x-1/2)) odd polynomial ----
    const float xx = d * 0.2f;
    const float hh = xx - 0.5f;
    const float v  = hh * hh;
    float sp = fmaf(v, fmaf(v, fmaf(v, fmaf(v, 0.0821458866f, -0.599264529f),
                                    2.55016404f), -5.16771278f), 3.14159265f);
    const float cospix = -hh * sp;
    const float phi = (d < R_CUTF) ? 0.5f * (cospix + 1.0f) * pm : 0.f;

    // ---- spherical harmonics: channels [4h, 4h+4) ----
    const float um = (d != 0.f) ? inv : 0.f;
    const float ux = rx * um * pm;
    const float uy = ry * um * pm;
    const float uz = rz * um * pm;

    const float scale = phi * pm * pmi;

    const float lo0 = C1 * uy;
    const float lo1 = C1 * uz;
    const float lo2 = C1 * ux;
    const float lo3 = C2A * ux * uy;
    const float hi0 = C2A * uy * uz;
    const float hi1 = C2B * fmaf(3.f, uz * uz, -1.f);
    const float hi2 = C2A * ux * uz;
    const float hi3 = C2C * (ux * ux - uy * uy);

    float val0 = (h ? hi0 : lo0) * scale;
    float val1 = (h ? hi1 : lo1) * scale;
    float val2 = (h ? hi2 : lo2) * scale;
    float val3 = (h ? hi3 : lo3) * scale;

    // ---- segmented reduction within 16-lane halves (idx_i sorted) ----
    int ii = i;
    const unsigned full = 0xffffffffu;
    const unsigned l16  = lane & 15u;
    #pragma unroll
    for (int off = 2; off <= 8; off <<= 1) {
        int   i2 = __shfl_down_sync(full, ii, off, 16);
        bool take = (l16 + off < 16) && (i2 == ii);
        float f0 = __shfl_down_sync(full, val0, off, 16);
        float f1 = __shfl_down_sync(full, val1, off, 16);
        float f2 = __shfl_down_sync(full, val2, off, 16);
        float f3 = __shfl_down_sync(full, val3, off, 16);
        if (take) { val0 += f0; val1 += f1; val2 += f2; val3 += f3; }
    }
    int iprev = __shfl_up_sync(full, ii, 2, 16);
    bool leader = (l16 < 2) || (iprev != ii);
    if (leader) {
        float4* dst = (float4*)(chi_out + (unsigned)ii * 8u + 4u * h);
        atomicAdd(dst, make_float4(val0, val1, val2, val3));
    }

    // ---- drain DMA; last block resets counters for the next graph replay ----
    if (tid == 0) {
        asm volatile("cp.async.bulk.wait_group 0;" ::: "memory");
        unsigned r = atomicAdd(&g_done_ctr, 1u);
        if (r == gridDim.x - 1u) {
            g_init_ctr = 0u;
            g_done_ctr = 0u;
            __threadfence();
        }
    }
}

// ---------------------------------------------------------------------------
// Fallback path (round-10 two-kernel structure) for shapes the fused kernel
// doesn't cover.
// ---------------------------------------------------------------------------
__global__ void __launch_bounds__(256)
init_kernel(const float* __restrict__ R, float4* __restrict__ chi4, int n)
{
    int i = blockIdx.x * 256 + threadIdx.x;
    if (i < n) {
        g_R4[i] = make_float4(R[3*(size_t)i], R[3*(size_t)i + 1],
                              R[3*(size_t)i + 2], 0.f);
        const float4 z = make_float4(0.f, 0.f, 0.f, 0.f);
        chi4[2*(size_t)i]     = z;
        chi4[2*(size_t)i + 1] = z;
    }
}

__global__ void __launch_bounds__(256, 6)
geo_generic(const float* __restrict__ pair_mask,
            const float* __restrict__ point_mask,
            const int*   __restrict__ idx_i,
            const int*   __restrict__ idx_j,
            float* __restrict__ rbf_out,
            float* __restrict__ chi_out,
            int n_pairs)
{
    __shared__ __align__(16) float tile[PAIRS_PER_BLOCK * NRBF];

    const unsigned tid  = threadIdx.x;
    const unsigned lane = tid & 31u;
    const unsigned s    = tid >> 1;
    const unsigned h    = tid & 1u;
    const unsigned p    = blockIdx.x * (unsigned)PAIRS_PER_BLOCK + s;
    const bool valid    = (p < (unsigned)n_pairs);

    int i = 0, j = 0;
    float pm = 0.f, pmi = 0.f;
    if (valid) {
        i  = __ldg(idx_i + p);
        j  = __ldg(idx_j + p);
        pm = __ldg(pair_mask + p);
        pmi = __ldg(point_mask + i);
    }

    float rx = 0.f, ry = 0.f, rz = 0.f;
    if (valid) {
        const float4 a = __ldg(&g_R4[j]);
        const float4 b = __ldg(&g_R4[i]);
        rx = (a.x - b.x) * pm;
        ry = (a.y - b.y) * pm;
        rz = (a.z - b.z) * pm;
    }

    const float sq  = fmaf(rx, rx, fmaf(ry, ry, rz * rz));
    const float inv = (sq > 0.f) ? rsqrtf(sq) : 0.f;
    const float d   = sq * inv * pm;

    const float cm   = (float)(16u * h + 8u) * STEP;
    const float u0   = (d - cm) * INV_W;
    const float u0r  = fminf(fmaxf(u0, -U0_MAX), U0_MAX);
    const float kill = (fabsf(u0) < U0_MAX) ? pm : 0.f;
    const float A  = fast_exp(-0.5f * u0r * u0r) * kill;
    const float qu = fast_exp(fmaf(u0r, S_RATIO, -HALF_S2));
    float rq = __uint_as_float(0x7EF311C3u - __float_as_uint(qu));
    rq = rq * (2.0f - qu * rq);
    rq = rq * (2.0f - qu * rq);
    rq = rq * (2.0f - qu * rq);
    const float qd = G_CONST * rq;

    float x[16];
    x[8] = A;
    { float r = A, q = qd;
      #pragma unroll
      for (int m = 7; m >= 0; --m) { r *= q; q *= G_CONST; x[m] = r; } }
    { float r = A, q = qu;
      #pragma unroll
      for (int m = 9; m < 16; ++m) { r *= q; q *= G_CONST; x[m] = r; } }

    {
        const float4 Q0 = make_float4(x[0],  x[1],  x[2],  x[3]);
        const float4 Q1 = make_float4(x[4],  x[5],  x[6],  x[7]);
        const float4 Q2 = make_float4(x[8],  x[9],  x[10], x[11]);
        const float4 Q3 = make_float4(x[12], x[13], x[14], x[15]);
        char* rowp = (char*)tile + (s * 128u + h * 64u);
        #pragma unroll
        for (unsigned t = 0; t < 4; ++t) {
            unsigned q = (t + s) & 3u;
            float4 a0 = (q & 1u) ? Q1 : Q0;
            float4 a1 = (q & 1u) ? Q3 : Q2;
            float4 r  = (q & 2u) ? a1 : a0;
            *(float4*)(rowp + q * 16u) = r;
        }
    }

    __syncthreads();
    if (tid == 0) {
        asm volatile("fence.proxy.async.shared::cta;" ::: "memory");
        size_t p0 = (size_t)blockIdx.x * PAIRS_PER_BLOCK;
        long long rows = (long long)n_pairs - (long long)p0;
        int nrows = (rows >= PAIRS_PER_BLOCK) ? PAIRS_PER_BLOCK : (int)rows;
        unsigned bytes = (unsigned)nrows * (NRBF * 4);
        uint32_t saddr;
        asm("{ .reg .u64 t; cvta.to.shared.u64 t, %1; cvt.u32.u64 %0, t; }"
            : "=r"(saddr) : "l"(tile));
        unsigned long long gaddr = (unsigned long long)(rbf_out + p0 * NRBF);
        asm volatile("cp.async.bulk.global.shared::cta.bulk_group [%0], [%1], %2;"
                     :: "l"(gaddr), "r"(saddr), "r"(bytes) : "memory");
        asm volatile("cp.async.bulk.commit_group;" ::: "memory");
    }

    const float xx = d * 0.2f;
    const float hh = xx - 0.5f;
    const float v  = hh * hh;
    float sp = fmaf(v, fmaf(v, fmaf(v, fmaf(v, 0.0821458866f, -0.599264529f),
                                    2.55016404f), -5.16771278f), 3.14159265f);
    const float cospix = -hh * sp;
    const float phi = (d < R_CUTF) ? 0.5f * (cospix + 1.0f) * pm : 0.f;

    const float um = (d != 0.f) ? inv : 0.f;
    const float ux = rx * um * pm;
    const float uy = ry * um * pm;
    const float uz = rz * um * pm;
    const float scale = phi * pm * pmi;

    const float lo0 = C1 * uy;
    const float lo1 = C1 * uz;
    const float lo2 = C1 * ux;
    const float lo3 = C2A * ux * uy;
    const float hi0 = C2A * uy * uz;
    const float hi1 = C2B * fmaf(3.f, uz * uz, -1.f);
    const float hi2 = C2A * ux * uz;
    const float hi3 = C2C * (ux * ux - uy * uy);

    float val0 = (h ? hi0 : lo0) * scale;
    float val1 = (h ? hi1 : lo1) * scale;
    float val2 = (h ? hi2 : lo2) * scale;
    float val3 = (h ? hi3 : lo3) * scale;

    int ii = valid ? i : -1;
    const unsigned full = 0xffffffffu;
    const unsigned l16  = lane & 15u;
    #pragma unroll
    for (int off = 2; off <= 8; off <<= 1) {
        int   i2 = __shfl_down_sync(full, ii, off, 16);
        bool take = (l16 + off < 16) && (i2 == ii);
        float f0 = __shfl_down_sync(full, val0, off, 16);
        float f1 = __shfl_down_sync(full, val1, off, 16);
        float f2 = __shfl_down_sync(full, val2, off, 16);
        float f3 = __shfl_down_sync(full, val3, off, 16);
        if (take) { val0 += f0; val1 += f1; val2 += f2; val3 += f3; }
    }
    int iprev = __shfl_up_sync(full, ii, 2, 16);
    bool leader = (l16 < 2) || (iprev != ii);
    if (leader && valid) {
        float4* dst = (float4*)(chi_out + (unsigned)ii * 8u + 4u * h);
        atomicAdd(dst, make_float4(val0, val1, val2, val3));
    }

    if (tid == 0) {
        asm volatile("cp.async.bulk.wait_group 0;" ::: "memory");
    }
}

extern "C" void kernel_launch(void* const* d_in, const int* in_sizes, int n_in,
                              void* d_out, int out_size)
{
    const float* R          = (const float*)d_in[0];
    const float* pair_mask  = (const float*)d_in[1];
    const float* point_mask = (const float*)d_in[2];
    const int*   idx_i      = (const int*)d_in[3];
    const int*   idx_j      = (const int*)d_in[4];

    const int n_pairs = in_sizes[1];
    const int n       = in_sizes[2];

    float* rbf_out = (float*)d_out;
    float* chi_out = rbf_out + (size_t)n_pairs * NRBF;

    int blocks = (n_pairs + PAIRS_PER_BLOCK - 1) / PAIRS_PER_BLOCK;
    bool fused_ok = (n_pairs % PAIRS_PER_BLOCK == 0) && (n <= RCAP) &&
                    (blocks >= 2 * INIT_BLOCKS);

    if (fused_ok) {
        geo_fused<<<blocks, 256>>>(R, pair_mask, point_mask, idx_i, idx_j,
                                   rbf_out, chi_out, n);
    } else {
        init_kernel<<<(n + 255) / 256, 256>>>(R, (float4*)chi_out, n);
        geo_generic<<<blocks, 256>>>(pair_mask, point_mask, idx_i, idx_j,
                                     rbf_out, chi_out, n_pairs);
    }
}

// round 13
// speedup vs baseline: 1.3290x; 1.3290x over previous
#include <cuda_runtime.h>
#include <cuda.h>
#include <dlfcn.h>
#include <math.h>
#include <string.h>
#include <stdint.h>

#define NRBF 32
#define RCAP 131072
__device__ float4 g_R4[RCAP];

// step = 5/31, width = 5/32
#define STEP      (0.16129032258064516f)
#define INV_W     (6.4f)
#define S_RATIO   (1.03225806451612903f)   // step/width
#define HALF_S2   (0.53277835587929240f)   // 0.5*(step/width)^2
#define G_CONST   (0.34453600290f)         // exp(-(step/width)^2)
#define R_CUTF    (5.0f)
#define U0_MAX    (13.0f)

#define C1  (0.48860251190291992f)
#define C2A (1.09254843059207907f)
#define C2B (0.31539156525252005f)
#define C2C (0.54627421529603953f)

#define PAIRS_PER_BLOCK 128

// FMA/ALU-only expf (no MUFU). Valid for x in [-85, +14].
__device__ __forceinline__ float fast_exp(float x) {
    float t  = x * 1.44269504f;
    float fi = rintf(t);
    int   ei = (int)fi;
    float g  = fmaf(fi, -0.693147182f, x);
    float p  = 1.9875691500e-4f;
    p = fmaf(p, g, 1.3981999507e-3f);
    p = fmaf(p, g, 8.3334519073e-3f);
    p = fmaf(p, g, 4.1665795894e-2f);
    p = fmaf(p, g, 1.6666665459e-1f);
    p = fmaf(p, g, 5.0000001201e-1f);
    float e = fmaf(g * g, p, g) + 1.0f;
    return __int_as_float(__float_as_int(e) + (ei << 23));
}

// init: pack R into float4 table + zero chi (separate launch: g_R4 stays
// strictly read-only in the hot kernel, so __ldg there is legal).
__global__ void __launch_bounds__(256)
init_kernel(const float* __restrict__ R, float4* __restrict__ chi4, int n)
{
    int i = blockIdx.x * 256 + threadIdx.x;
    if (i < n) {
        g_R4[i] = make_float4(R[3*(size_t)i], R[3*(size_t)i + 1],
                              R[3*(size_t)i + 2], 0.f);
        const float4 z = make_float4(0.f, 0.f, 0.f, 0.f);
        chi4[2*(size_t)i]     = z;
        chi4[2*(size_t)i + 1] = z;
    }
}

// 2 threads per pair. FULL: no tail guards. USE_TMA: SW128-swizzled STS
// (1 XOR per store, no SEL tree) + de-swizzling TMA tensor store.
template <bool FULL, bool USE_TMA>
__global__ void __launch_bounds__(256, 6)
geo_kernel(const float* __restrict__ pair_mask,
           const float* __restrict__ point_mask,
           const int*   __restrict__ idx_i,
           const int*   __restrict__ idx_j,
           float* __restrict__ rbf_out,
           float* __restrict__ chi_out,
           int n_pairs,
           const __grid_constant__ CUtensorMap tmap)
{
    __shared__ __align__(1024) float tile[PAIRS_PER_BLOCK * NRBF];

    const unsigned tid  = threadIdx.x;
    const unsigned lane = tid & 31u;
    const unsigned s    = tid >> 1;
    const unsigned h    = tid & 1u;
    const unsigned p    = blockIdx.x * (unsigned)PAIRS_PER_BLOCK + s;
    const bool valid    = FULL || (p < (unsigned)n_pairs);

    int i = 0, j = 0;
    float pm = 0.f, pmi = 0.f;
    if (valid) {
        i   = __ldg(idx_i + p);
        j   = __ldg(idx_j + p);
        pm  = __ldg(pair_mask + p);
        pmi = __ldg(point_mask + i);
    }

    float rx = 0.f, ry = 0.f, rz = 0.f;
    if (valid) {
        const float4 a = __ldg(&g_R4[j]);
        const float4 b = __ldg(&g_R4[i]);
        rx = (a.x - b.x) * pm;
        ry = (a.y - b.y) * pm;
        rz = (a.z - b.z) * pm;
    }

    const float sq  = fmaf(rx, rx, fmaf(ry, ry, rz * rz));
    const float inv = (sq > 0.f) ? rsqrtf(sq) : 0.f;
    const float d   = sq * inv * pm;

    // ---- rbf half-row: anchor at k = 16h+8, two-sided ladder ----
    const float cm   = (float)(16u * h + 8u) * STEP;
    const float u0   = (d - cm) * INV_W;
    const float u0r  = fminf(fmaxf(u0, -U0_MAX), U0_MAX);
    const float kill = (fabsf(u0) < U0_MAX) ? pm : 0.f;
    const float A  = fast_exp(-0.5f * u0r * u0r) * kill;
    const float qu = fast_exp(fmaf(u0r, S_RATIO, -HALF_S2));
    float rq = __uint_as_float(0x7EF311C3u - __float_as_uint(qu));
    rq = rq * (2.0f - qu * rq);
    rq = rq * (2.0f - qu * rq);
    rq = rq * (2.0f - qu * rq);
    const float qd = G_CONST * rq;

    float x[16];
    x[8] = A;
    {
        float r = A, q = qd;
        #pragma unroll
        for (int m = 7; m >= 0; --m) { r *= q; q *= G_CONST; x[m] = r; }
    }
    {
        float r = A, q = qu;
        #pragma unroll
        for (int m = 9; m < 16; ++m) { r *= q; q *= G_CONST; x[m] = r; }
    }

    const float4 Q0 = make_float4(x[0],  x[1],  x[2],  x[3]);
    const float4 Q1 = make_float4(x[4],  x[5],  x[6],  x[7]);
    const float4 Q2 = make_float4(x[8],  x[9],  x[10], x[11]);
    const float4 Q3 = make_float4(x[12], x[13], x[14], x[15]);

    if (USE_TMA) {
        // SW128-swizzled STS: addr = s*128 + ((4h+q) ^ (s&7))*16.
        // Per 8-lane STS.128 phase all 8 chunks distinct -> conflict-free.
        unsigned pbase = (tid * 64u) ^ ((s & 7u) << 4);
        char* bp = (char*)tile;
        *(float4*)(bp + (pbase ^  0u)) = Q0;
        *(float4*)(bp + (pbase ^ 16u)) = Q1;
        *(float4*)(bp + (pbase ^ 32u)) = Q2;
        *(float4*)(bp + (pbase ^ 48u)) = Q3;
    } else {
        // rotated-order STS (round-10 proven path)
        char* rowp = (char*)tile + (s * 128u + h * 64u);
        #pragma unroll
        for (unsigned t = 0; t < 4; ++t) {
            unsigned q = (t + s) & 3u;
            float4 a0 = (q & 1u) ? Q1 : Q0;
            float4 a1 = (q & 1u) ? Q3 : Q2;
            float4 r  = (q & 2u) ? a1 : a0;
            *(float4*)(rowp + q * 16u) = r;
        }
    }

    // ---- issue the async store NOW; chi work below overlaps it ----
    __syncthreads();
    if (tid == 0) {
        asm volatile("fence.proxy.async.shared::cta;" ::: "memory");
        uint32_t saddr;
        asm("{ .reg .u64 t; cvta.to.shared.u64 t, %1; cvt.u32.u64 %0, t; }"
            : "=r"(saddr) : "l"(tile));
        if (USE_TMA) {
            int row0 = (int)(blockIdx.x * (unsigned)PAIRS_PER_BLOCK);
            asm volatile(
                "cp.async.bulk.tensor.2d.global.shared::cta.tile.bulk_group "
                "[%0, {%1, %2}], [%3];"
                :: "l"(&tmap), "r"(0), "r"(row0), "r"(saddr) : "memory");
        } else {
            size_t p0 = (size_t)blockIdx.x * PAIRS_PER_BLOCK;
            unsigned bytes;
            if (FULL) {
                bytes = PAIRS_PER_BLOCK * NRBF * 4;
            } else {
                long long rows = (long long)n_pairs - (long long)p0;
                int nrows = (rows >= PAIRS_PER_BLOCK) ? PAIRS_PER_BLOCK : (int)rows;
                bytes = (unsigned)nrows * (NRBF * 4);
            }
            unsigned long long gaddr = (unsigned long long)(rbf_out + p0 * NRBF);
            asm volatile("cp.async.bulk.global.shared::cta.bulk_group [%0], [%1], %2;"
                         :: "l"(gaddr), "r"(saddr), "r"(bytes) : "memory");
        }
        asm volatile("cp.async.bulk.commit_group;" ::: "memory");
    }

    // ---- phi (cutoff): cos(pi*x) = -sin(pi*(x-1/2)) odd polynomial ----
    const float xx = d * 0.2f;
    const float hh = xx - 0.5f;
    const float v  = hh * hh;
    float sp = fmaf(v, fmaf(v, fmaf(v, fmaf(v, 0.0821458866f, -0.599264529f),
                                    2.55016404f), -5.16771278f), 3.14159265f);
    const float cospix = -hh * sp;
    const float phi = (d < R_CUTF) ? 0.5f * (cospix + 1.0f) * pm : 0.f;

    // ---- spherical harmonics: channels [4h, 4h+4) ----
    const float um = (d != 0.f) ? inv : 0.f;
    const float ux = rx * um * pm;
    const float uy = ry * um * pm;
    const float uz = rz * um * pm;

    const float scale = phi * pm * pmi;

    const float lo0 = C1 * uy;
    const float lo1 = C1 * uz;
    const float lo2 = C1 * ux;
    const float lo3 = C2A * ux * uy;
    const float hi0 = C2A * uy * uz;
    const float hi1 = C2B * fmaf(3.f, uz * uz, -1.f);
    const float hi2 = C2A * ux * uz;
    const float hi3 = C2C * (ux * ux - uy * uy);

    float val0 = (h ? hi0 : lo0) * scale;
    float val1 = (h ? hi1 : lo1) * scale;
    float val2 = (h ? hi2 : lo2) * scale;
    float val3 = (h ? hi3 : lo3) * scale;

    // ---- segmented reduction within 16-lane halves (idx_i sorted) ----
    int ii = valid ? i : -1;
    const unsigned full = 0xffffffffu;
    const unsigned l16  = lane & 15u;
    #pragma unroll
    for (int off = 2; off <= 8; off <<= 1) {
        int   i2 = __shfl_down_sync(full, ii, off, 16);
        bool take = (l16 + off < 16) && (i2 == ii);
        float f0 = __shfl_down_sync(full, val0, off, 16);
        float f1 = __shfl_down_sync(full, val1, off, 16);
        float f2 = __shfl_down_sync(full, val2, off, 16);
        float f3 = __shfl_down_sync(full, val3, off, 16);
        if (take) { val0 += f0; val1 += f1; val2 += f2; val3 += f3; }
    }
    int iprev = __shfl_up_sync(full, ii, 2, 16);
    bool leader = (l16 < 2) || (iprev != ii);
    if (leader && valid) {
        float4* dst = (float4*)(chi_out + (unsigned)ii * 8u + 4u * h);
        atomicAdd(dst, make_float4(val0, val1, val2, val3));
    }

    // ---- drain the async store last ----
    if (tid == 0) {
        asm volatile("cp.async.bulk.wait_group 0;" ::: "memory");
    }
}

// ---------------------------------------------------------------------------
// Host
// ---------------------------------------------------------------------------
typedef CUresult (*PFN_encodeTiled)(
    CUtensorMap*, CUtensorMapDataType, cuuint32_t, void*,
    const cuuint64_t*, const cuuint64_t*, const cuuint32_t*, const cuuint32_t*,
    CUtensorMapInterleave, CUtensorMapSwizzle, CUtensorMapL2promotion,
    CUtensorMapFloatOOBfill);

static PFN_encodeTiled get_encode_fn()
{
    static PFN_encodeTiled fn = nullptr;
    static bool tried = false;
    if (!tried) {
        tried = true;
        void* hdl = dlopen("libcuda.so.1", RTLD_LAZY | RTLD_GLOBAL);
        if (!hdl) hdl = dlopen("libcuda.so", RTLD_LAZY | RTLD_GLOBAL);
        if (hdl) fn = (PFN_encodeTiled)dlsym(hdl, "cuTensorMapEncodeTiled");
    }
    return fn;
}

extern "C" void kernel_launch(void* const* d_in, const int* in_sizes, int n_in,
                              void* d_out, int out_size)
{
    const float* R          = (const float*)d_in[0];
    const float* pair_mask  = (const float*)d_in[1];
    const float* point_mask = (const float*)d_in[2];
    const int*   idx_i      = (const int*)d_in[3];
    const int*   idx_j      = (const int*)d_in[4];

    const int n_pairs = in_sizes[1];
    const int n       = in_sizes[2];

    float* rbf_out = (float*)d_out;
    float* chi_out = rbf_out + (size_t)n_pairs * NRBF;

    init_kernel<<<(n + 255) / 256, 256>>>(R, (float4*)chi_out, n);

    // Try to build the de-swizzling TMA descriptor (host-side, no stream op).
    CUtensorMap tmap;
    memset(&tmap, 0, sizeof(tmap));
    bool use_tma = false;
    PFN_encodeTiled enc = get_encode_fn();
    if (enc) {
        cuuint64_t dims[2]    = {32, (cuuint64_t)n_pairs};
        cuuint64_t strides[1] = {NRBF * 4};   // 128 B per row
        cuuint32_t box[2]     = {32, PAIRS_PER_BLOCK};
        cuuint32_t es[2]      = {1, 1};
        CUresult r = enc(&tmap, CU_TENSOR_MAP_DATA_TYPE_FLOAT32, 2,
                         (void*)rbf_out, dims, strides, box, es,
                         CU_TENSOR_MAP_INTERLEAVE_NONE,
                         CU_TENSOR_MAP_SWIZZLE_128B,
                         CU_TENSOR_MAP_L2_PROMOTION_L2_128B,
                         CU_TENSOR_MAP_FLOAT_OOB_FILL_NONE);
        use_tma = (r == CUDA_SUCCESS);
    }

    int blocks = (n_pairs + PAIRS_PER_BLOCK - 1) / PAIRS_PER_BLOCK;
    const bool full = (n_pairs % PAIRS_PER_BLOCK) == 0;

    if (full && use_tma) {
        geo_kernel<true, true><<<blocks, 256>>>(pair_mask, point_mask, idx_i,
                                                idx_j, rbf_out, chi_out,
                                                n_pairs, tmap);
    } else if (full) {
        geo_kernel<true, false><<<blocks, 256>>>(pair_mask, point_mask, idx_i,
                                                 idx_j, rbf_out, chi_out,
                                                 n_pairs, tmap);
    } else if (use_tma) {
        geo_kernel<false, true><<<blocks, 256>>>(pair_mask, point_mask, idx_i,
                                                 idx_j, rbf_out, chi_out,
                                                 n_pairs, tmap);
    } else {
        geo_kernel<false, false><<<blocks, 256>>>(pair_mask, point_mask, idx_i,
                                                  idx_j, rbf_out, chi_out,
                                                  n_pairs, tmap);
    }
}